// round 3
// baseline (speedup 1.0000x reference)
#include <cuda_runtime.h>
#include <cstdint>

// Problem constants (shapes are fixed by the dataset)
#define NMAX    100000
#define IN_DIM  32
#define HID     64
#define NGRAPHS 128
#define LAT     32

// Scratch (device globals — allocation-free rule). 16B-aligned for float4/red.v4.
__device__ __align__(16) float g_h[(size_t)NMAX * HID];
__device__ __align__(16) float g_agg[(size_t)NMAX * HID];
__device__ __align__(16) float g_pooled[NGRAPHS * HID];

__device__ __forceinline__ void red_add_v4(float* p, float4 v) {
    asm volatile("red.global.add.v4.f32 [%0], {%1,%2,%3,%4};"
                 :: "l"(p), "f"(v.x), "f"(v.y), "f"(v.z), "f"(v.w)
                 : "memory");
}

// ---------------------------------------------------------------------------
// Zero kernels
// ---------------------------------------------------------------------------
__global__ void k_zero_agg(int n4) {
    int i = blockIdx.x * blockDim.x + threadIdx.x;
    if (i < n4) reinterpret_cast<float4*>(g_agg)[i] = make_float4(0.f, 0.f, 0.f, 0.f);
}

__global__ void k_zero_pooled() {
    int i = blockIdx.x * blockDim.x + threadIdx.x;
    if (i < NGRAPHS * HID / 4)
        reinterpret_cast<float4*>(g_pooled)[i] = make_float4(0.f, 0.f, 0.f, 0.f);
}

// ---------------------------------------------------------------------------
// Shared 4x4-register-blocked GEMM tile core.
// Block: 256 threads; tile: 64 nodes x 64 out-features.
// fq = tid&15 (feature quad, fast-varying across warp -> conflict-free w loads,
// broadcast sA loads), ng = tid>>4 (node group of 4).
// ---------------------------------------------------------------------------
template<int K>
__device__ __forceinline__ void gemm44(const float* __restrict__ sA, int lda,
                                       const float* __restrict__ sW,
                                       int fq, int ng, float acc[4][4]) {
#pragma unroll
    for (int k = 0; k < K; k += 4) {
        float4 w0 = *reinterpret_cast<const float4*>(&sW[(k + 0) * HID + 4 * fq]);
        float4 w1 = *reinterpret_cast<const float4*>(&sW[(k + 1) * HID + 4 * fq]);
        float4 w2 = *reinterpret_cast<const float4*>(&sW[(k + 2) * HID + 4 * fq]);
        float4 w3 = *reinterpret_cast<const float4*>(&sW[(k + 3) * HID + 4 * fq]);
#pragma unroll
        for (int n = 0; n < 4; n++) {
            float4 a = *reinterpret_cast<const float4*>(&sA[(ng * 4 + n) * lda + k]);
            acc[n][0] += a.x * w0.x + a.y * w1.x + a.z * w2.x + a.w * w3.x;
            acc[n][1] += a.x * w0.y + a.y * w1.y + a.z * w2.y + a.w * w3.y;
            acc[n][2] += a.x * w0.z + a.y * w1.z + a.z * w2.z + a.w * w3.z;
            acc[n][3] += a.x * w0.w + a.y * w1.w + a.z * w2.w + a.w * w3.w;
        }
    }
}

// ---------------------------------------------------------------------------
// Input projection: h = x @ w_in + b_in        [N,32] @ [32,64]
// ---------------------------------------------------------------------------
__global__ __launch_bounds__(256) void k_proj(const float* __restrict__ x,
                                              const float* __restrict__ w_in,
                                              const float* __restrict__ b_in,
                                              int nNodes) {
    __shared__ __align__(16) float sX[64 * IN_DIM];
    __shared__ __align__(16) float sW[IN_DIM * HID];
    int tid = threadIdx.x;
    int nb = blockIdx.x * 64;

    for (int i = tid; i < 64 * IN_DIM; i += 256) {
        int n = nb + i / IN_DIM;
        sX[i] = (n < nNodes) ? x[(size_t)nb * IN_DIM + i] : 0.f;
    }
    for (int i = tid; i < IN_DIM * HID; i += 256) sW[i] = w_in[i];
    __syncthreads();

    int fq = tid & 15, ng = tid >> 4;
    float acc[4][4];
    float4 bb = *reinterpret_cast<const float4*>(b_in + 4 * fq);
#pragma unroll
    for (int n = 0; n < 4; n++) {
        acc[n][0] = bb.x; acc[n][1] = bb.y; acc[n][2] = bb.z; acc[n][3] = bb.w;
    }
    gemm44<IN_DIM>(sX, IN_DIM, sW, fq, ng, acc);

#pragma unroll
    for (int n = 0; n < 4; n++) {
        int node = nb + ng * 4 + n;
        if (node < nNodes)
            *reinterpret_cast<float4*>(&g_h[(size_t)node * HID + 4 * fq]) =
                make_float4(acc[n][0], acc[n][1], acc[n][2], acc[n][3]);
    }
}

// ---------------------------------------------------------------------------
// Edge scatter: agg[dst] += h[src].  16 threads per edge, vec4 reductions.
// edge_index is int32 (JAX x64 disabled -> int64 request silently becomes i32)
// ---------------------------------------------------------------------------
__global__ __launch_bounds__(256) void k_scatter(const int* __restrict__ ei,
                                                 int nEdges, int nNodes) {
    long long t = (long long)blockIdx.x * blockDim.x + threadIdx.x;
    int e = (int)(t >> 4);
    int lane = (int)(t & 15);
    if (e >= nEdges) return;
    int src = __ldg(&ei[e]);
    int dst = __ldg(&ei[(size_t)nEdges + e]);
    if ((unsigned)src >= (unsigned)nNodes || (unsigned)dst >= (unsigned)nNodes) return;
    float4 v = *reinterpret_cast<const float4*>(&g_h[(size_t)src * HID + 4 * lane]);
    red_add_v4(&g_agg[(size_t)dst * HID + 4 * lane], v);
}

// ---------------------------------------------------------------------------
// Fused GIN MLP: h = relu(relu((h+agg)@w1+b1)@w2+b2) + h   (in place on g_h)
// ---------------------------------------------------------------------------
__global__ __launch_bounds__(256) void k_mlp(const float* __restrict__ w1,
                                             const float* __restrict__ b1,
                                             const float* __restrict__ w2,
                                             const float* __restrict__ b2,
                                             int nNodes) {
    __shared__ __align__(16) float sW[HID * HID];      // 16 KB, reused for w1 then w2
    __shared__ __align__(16) float sIn[64 * HID];      // 16 KB
    __shared__ __align__(16) float sMid[64 * HID];     // 16 KB
    int tid = threadIdx.x;
    int nb = blockIdx.x * 64;

    for (int i = tid; i < HID * HID; i += 256) sW[i] = w1[i];
    for (int i = tid; i < 64 * HID; i += 256) {
        int n = nb + i / HID;
        size_t idx = (size_t)nb * HID + i;
        sIn[i] = (n < nNodes) ? g_h[idx] + g_agg[idx] : 0.f;
    }
    __syncthreads();

    int fq = tid & 15, ng = tid >> 4;
    float acc[4][4];

    // phase 1: mid = relu(in @ w1 + b1)
    {
        float4 bb = *reinterpret_cast<const float4*>(b1 + 4 * fq);
#pragma unroll
        for (int n = 0; n < 4; n++) {
            acc[n][0] = bb.x; acc[n][1] = bb.y; acc[n][2] = bb.z; acc[n][3] = bb.w;
        }
        gemm44<HID>(sIn, HID, sW, fq, ng, acc);
#pragma unroll
        for (int n = 0; n < 4; n++) {
            float4 r = make_float4(fmaxf(acc[n][0], 0.f), fmaxf(acc[n][1], 0.f),
                                   fmaxf(acc[n][2], 0.f), fmaxf(acc[n][3], 0.f));
            *reinterpret_cast<float4*>(&sMid[(ng * 4 + n) * HID + 4 * fq]) = r;
        }
    }
    __syncthreads();

    for (int i = tid; i < HID * HID; i += 256) sW[i] = w2[i];
    __syncthreads();

    // phase 2: h = relu(mid @ w2 + b2) + h_skip
    {
        float4 bb = *reinterpret_cast<const float4*>(b2 + 4 * fq);
#pragma unroll
        for (int n = 0; n < 4; n++) {
            acc[n][0] = bb.x; acc[n][1] = bb.y; acc[n][2] = bb.z; acc[n][3] = bb.w;
        }
        gemm44<HID>(sMid, HID, sW, fq, ng, acc);
#pragma unroll
        for (int n = 0; n < 4; n++) {
            int node = nb + ng * 4 + n;
            if (node < nNodes) {
                size_t idx = (size_t)node * HID + 4 * fq;
                float4 skip = *reinterpret_cast<const float4*>(&g_h[idx]);
                float4 r = make_float4(fmaxf(acc[n][0], 0.f) + skip.x,
                                       fmaxf(acc[n][1], 0.f) + skip.y,
                                       fmaxf(acc[n][2], 0.f) + skip.z,
                                       fmaxf(acc[n][3], 0.f) + skip.w);
                *reinterpret_cast<float4*>(&g_h[idx]) = r;
            }
        }
    }
}

// ---------------------------------------------------------------------------
// Global add-pool: pooled[batch[n]] += h[n]   (batch is int32)
// ---------------------------------------------------------------------------
__global__ __launch_bounds__(256) void k_pool(const int* __restrict__ batch,
                                              int nNodes) {
    long long t = (long long)blockIdx.x * blockDim.x + threadIdx.x;
    int node = (int)(t >> 4);
    int lane = (int)(t & 15);
    if (node >= nNodes) return;
    int g = __ldg(&batch[node]);
    if ((unsigned)g >= NGRAPHS) return;
    float4 v = *reinterpret_cast<const float4*>(&g_h[(size_t)node * HID + 4 * lane]);
    red_add_v4(&g_pooled[g * HID + 4 * lane], v);
}

// ---------------------------------------------------------------------------
// Final: out = pooled @ w_fc + b_fc   [128,64] @ [64,32]
// ---------------------------------------------------------------------------
__global__ __launch_bounds__(256) void k_final(const float* __restrict__ w_fc,
                                               const float* __restrict__ b_fc,
                                               float* __restrict__ out) {
    int t = blockIdx.x * blockDim.x + threadIdx.x;   // 0..4095
    if (t >= NGRAPHS * LAT) return;
    int g = t >> 5;
    int l = t & 31;
    float acc = b_fc[l];
#pragma unroll
    for (int k = 0; k < HID; k++)
        acc += g_pooled[g * HID + k] * w_fc[k * LAT + l];
    out[t] = acc;
}

// ---------------------------------------------------------------------------
// Launch
// ---------------------------------------------------------------------------
extern "C" void kernel_launch(void* const* d_in, const int* in_sizes, int n_in,
                              void* d_out, int out_size) {
    const float* x    = (const float*)d_in[0];
    const int*   ei   = (const int*)d_in[1];     // int32 (JAX default x64 off)
    const int*   batch= (const int*)d_in[2];     // int32
    const float* w_in = (const float*)d_in[3];
    const float* b_in = (const float*)d_in[4];
    const float* w1   = (const float*)d_in[5];
    const float* b1   = (const float*)d_in[6];
    const float* w2   = (const float*)d_in[7];
    const float* b2   = (const float*)d_in[8];
    const float* w_fc = (const float*)d_in[9];
    const float* b_fc = (const float*)d_in[10];
    float* out = (float*)d_out;

    int nNodes = in_sizes[0] / IN_DIM;
    int nEdges = in_sizes[1] / 2;
    if (nNodes > NMAX) nNodes = NMAX;

    int nodeBlocks = (nNodes + 63) / 64;
    int aggN4 = nNodes * HID / 4;
    int zeroBlocks = (aggN4 + 255) / 256;
    long long scatterThreads = (long long)nEdges * 16;
    int scatterBlocks = (int)((scatterThreads + 255) / 256);
    long long poolThreads = (long long)nNodes * 16;
    int poolBlocks = (int)((poolThreads + 255) / 256);

    k_zero_pooled<<<(NGRAPHS * HID / 4 + 255) / 256, 256>>>();
    k_proj<<<nodeBlocks, 256>>>(x, w_in, b_in, nNodes);

    for (int i = 0; i < 3; i++) {
        k_zero_agg<<<zeroBlocks, 256>>>(aggN4);
        k_scatter<<<scatterBlocks, 256>>>(ei, nEdges, nNodes);
        k_mlp<<<nodeBlocks, 256>>>(w1 + (size_t)i * HID * HID, b1 + (size_t)i * HID,
                                   w2 + (size_t)i * HID * HID, b2 + (size_t)i * HID,
                                   nNodes);
    }

    k_pool<<<poolBlocks, 256>>>(batch, nNodes);
    k_final<<<(NGRAPHS * LAT + 255) / 256, 256>>>(w_fc, b_fc, out);
}